// round 14
// baseline (speedup 1.0000x reference)
#include <cuda_runtime.h>
#include <cuda_bf16.h>
#include <math.h>

typedef unsigned long long ull;

#define SS 2048
#define BB 64
#define II 512
#define HH 512
#define G3 1536   // 3*H
#define LL 2

// ---- Scratch (allocation-free rule: __device__ globals) --------------------
__device__ float g_xlin[(size_t)SS * G3 * BB];   // [S,3H,B]
__device__ float g_T1  [(size_t)SS * HH * BB];   // [S,H,B] ys (both layers)
__device__ __nv_bfloat16 g_bhi[(size_t)SS * BB * II];  // X split hi
__device__ __nv_bfloat16 g_blo[(size_t)SS * BB * II];  // X split lo
__device__ __nv_bfloat16 g_whi[(size_t)G3 * II];
__device__ __nv_bfloat16 g_wlo[(size_t)G3 * II];
// h exchange, consumer-fragment-packed: [s][bg 4][w 8][1024 u32]
__device__ unsigned g_hx[(size_t)SS * 4 * 8 * 1024];
// per-CTA step flags: [bg 4][cg 32] x 8-u32 stride (32B each; 4 per 128B line)
__device__ unsigned g_flag[128 * 8];

// ---------------------------------------------------------------------------
// prep: split W (bf16 hi/lo), split X, reset flags — one kernel (launch-count
// control so ncu -s 5 lands on the layer-2 scan)
// ---------------------------------------------------------------------------
__global__ __launch_bounds__(256) void prep_layer(
    const float* __restrict__ X, const float* __restrict__ W,
    __nv_bfloat16* __restrict__ xh, __nv_bfloat16* __restrict__ xl,
    __nv_bfloat16* __restrict__ wh, __nv_bfloat16* __restrict__ wl)
{
    const unsigned NWB = (G3 * II) / 256;      // 3072
    unsigned bid = blockIdx.x;
    int tid = threadIdx.x;
    if (bid < NWB) {
        size_t i = (size_t)bid * 256 + tid;
        float v = W[i];
        __nv_bfloat16 h = __float2bfloat16(v);
        wh[i] = h; wl[i] = __float2bfloat16(v - __bfloat162float(h));
    } else if (bid == NWB) {
        for (int j = tid; j < 128 * 8; j += 256) g_flag[j] = 0;
    } else {
        size_t i = (size_t)(bid - NWB - 1) * 256 + tid;
        float v = X[i];
        __nv_bfloat16 h = __float2bfloat16(v);
        xh[i] = h; xl[i] = __float2bfloat16(v - __bfloat162float(h));
    }
}

// ---------------------------------------------------------------------------
__device__ __forceinline__ void mma_bf16(float* d, const unsigned* a, const unsigned* b)
{
    asm volatile(
        "mma.sync.aligned.m16n8k16.row.col.f32.bf16.bf16.f32 "
        "{%0,%1,%2,%3},{%4,%5,%6,%7},{%8,%9},{%0,%1,%2,%3};"
        : "+f"(d[0]), "+f"(d[1]), "+f"(d[2]), "+f"(d[3])
        : "r"(a[0]), "r"(a[1]), "r"(a[2]), "r"(a[3]), "r"(b[0]), "r"(b[1]));
}

__device__ __forceinline__ void ldmx4(unsigned* r, const __nv_bfloat16* p)
{
    unsigned addr = (unsigned)__cvta_generic_to_shared(p);
    asm volatile("ldmatrix.sync.aligned.m8n8.x4.shared.b16 {%0,%1,%2,%3}, [%4];"
                 : "=r"(r[0]), "=r"(r[1]), "=r"(r[2]), "=r"(r[3]) : "r"(addr));
}

__device__ __forceinline__ unsigned ld_acq(const unsigned* p)
{
    unsigned v;
    asm volatile("ld.acquire.gpu.global.u32 %0, [%1];" : "=r"(v) : "l"(p));
    return v;
}

__device__ __forceinline__ void st_rel(unsigned* p, unsigned v)
{
    asm volatile("st.release.gpu.global.u32 [%0], %1;" :: "l"(p), "r"(v) : "memory");
}

__device__ __forceinline__ float fast_ex2(float x)
{ float y; asm("ex2.approx.f32 %0, %1;" : "=f"(y) : "f"(x)); return y; }
__device__ __forceinline__ float fast_rcp(float x)
{ float y; asm("rcp.approx.f32 %0, %1;" : "=f"(y) : "f"(x)); return y; }
__device__ __forceinline__ float fsig(float x)
{ return fast_rcp(1.f + fast_ex2(-1.44269504f * x)); }
__device__ __forceinline__ float ftanh_(float x)
{ return fmaf(2.f, fast_rcp(1.f + fast_ex2(-2.88539008f * x)), -1.f); }

// pack float2 -> bf16x2 + residual pair
__device__ __forceinline__ void f2_hilo(float2 v, unsigned& hi, unsigned& lo)
{
    asm("cvt.rn.bf16x2.f32 %0, %1, %2;" : "=r"(hi) : "f"(v.y), "f"(v.x));
    __nv_bfloat162 hb = *reinterpret_cast<__nv_bfloat162*>(&hi);
    float rx = v.x - __bfloat162float(hb.x);
    float ry = v.y - __bfloat162float(hb.y);
    asm("cvt.rn.bf16x2.f32 %0, %1, %2;" : "=r"(lo) : "f"(ry), "f"(rx));
}

// ---------------------------------------------------------------------------
// xlinT[s, n, b] = sum_k W[n,k] * X[s,b,k] + bias[n]  (bf16x3 mma)
// BT=0: X rows [b][k].  BT=1: X stored [s][k][b].
// ---------------------------------------------------------------------------
#define BMN 128
#define BNB 64
#define BK  32
#define LDT 40

template <int BT>
__global__ __launch_bounds__(256, 2) void gemm_xlinT(
    const __nv_bfloat16* __restrict__ Whi, const __nv_bfloat16* __restrict__ Wlo,
    const __nv_bfloat16* __restrict__ Xhi, const __nv_bfloat16* __restrict__ Xlo,
    const float* __restrict__ bias, float* __restrict__ C)
{
    __shared__ __align__(16) __nv_bfloat16 sA[2][BMN * LDT];
    __shared__ __align__(16) __nv_bfloat16 sB[2][BNB * LDT];

    int tid  = threadIdx.x;
    int s    = blockIdx.x;
    int n0   = blockIdx.y * BMN;
    int w    = tid >> 5, lane = tid & 31;
    int wm   = w >> 1,   wn   = w & 1;

    const __nv_bfloat16* Xh = Xhi + (size_t)s * BB * II;
    const __nv_bfloat16* Xl = Xlo + (size_t)s * BB * II;

    float acc[2][4][4];
#pragma unroll
    for (int i = 0; i < 2; i++)
#pragma unroll
        for (int j = 0; j < 4; j++)
#pragma unroll
            for (int k = 0; k < 4; k++) acc[i][j][k] = 0.f;

    for (int k0 = 0; k0 < II; k0 += BK) {
        __syncthreads();
#pragma unroll
        for (int v = 0; v < 2; v++) {
            int fi = tid + v * 256;
            int r  = fi >> 2, kq = fi & 3;
            const uint4* gh = reinterpret_cast<const uint4*>(Whi + (size_t)(n0 + r) * II + k0);
            const uint4* gl = reinterpret_cast<const uint4*>(Wlo + (size_t)(n0 + r) * II + k0);
            reinterpret_cast<uint4*>(&sA[0][(size_t)r * LDT])[kq] = gh[kq];
            reinterpret_cast<uint4*>(&sA[1][(size_t)r * LDT])[kq] = gl[kq];
        }
        if (BT == 0) {
            int r = tid >> 2, kq = tid & 3;
            const uint4* gh = reinterpret_cast<const uint4*>(Xh + (size_t)r * II + k0);
            const uint4* gl = reinterpret_cast<const uint4*>(Xl + (size_t)r * II + k0);
            reinterpret_cast<uint4*>(&sB[0][(size_t)r * LDT])[kq] = gh[kq];
            reinterpret_cast<uint4*>(&sB[1][(size_t)r * LDT])[kq] = gl[kq];
        } else {
            int kk = tid >> 3;
            int bo = (tid & 7) * 8;
            uint4 vh = *reinterpret_cast<const uint4*>(Xh + (size_t)(k0 + kk) * BB + bo);
            uint4 vl = *reinterpret_cast<const uint4*>(Xl + (size_t)(k0 + kk) * BB + bo);
            const unsigned short* ph = reinterpret_cast<const unsigned short*>(&vh);
            const unsigned short* pl = reinterpret_cast<const unsigned short*>(&vl);
            unsigned short* s0 = reinterpret_cast<unsigned short*>(sB[0]);
            unsigned short* s1 = reinterpret_cast<unsigned short*>(sB[1]);
#pragma unroll
            for (int e = 0; e < 8; e++) {
                s0[(size_t)(bo + e) * LDT + kk] = ph[e];
                s1[(size_t)(bo + e) * LDT + kk] = pl[e];
            }
        }
        __syncthreads();

#pragma unroll
        for (int kh = 0; kh < 2; kh++) {
            int koff = kh * 16;
            unsigned af[2][2][4];
            unsigned bf[4][2][2];
            int q = lane >> 3, lr = lane & 7;
#pragma unroll
            for (int mt = 0; mt < 2; mt++) {
                const __nv_bfloat16* pa =
                    &sA[0][(size_t)(wm * 32 + mt * 16 + (q & 1) * 8 + lr) * LDT + koff + (q >> 1) * 8];
                ldmx4(af[mt][0], pa);
                ldmx4(af[mt][1], pa + BMN * LDT);
            }
#pragma unroll
            for (int j = 0; j < 2; j++) {
                int ntile = 2 * j + (q >> 1);
                const __nv_bfloat16* pb =
                    &sB[0][(size_t)(wn * 32 + ntile * 8 + lr) * LDT + koff + (q & 1) * 8];
                unsigned t[4];
                ldmx4(t, pb);
                bf[2 * j][0][0] = t[0]; bf[2 * j][0][1] = t[1];
                bf[2 * j + 1][0][0] = t[2]; bf[2 * j + 1][0][1] = t[3];
                ldmx4(t, pb + BNB * LDT);
                bf[2 * j][1][0] = t[0]; bf[2 * j][1][1] = t[1];
                bf[2 * j + 1][1][0] = t[2]; bf[2 * j + 1][1][1] = t[3];
            }
#pragma unroll
            for (int mt = 0; mt < 2; mt++)
#pragma unroll
                for (int nt = 0; nt < 4; nt++) {
                    mma_bf16(acc[mt][nt], af[mt][0], bf[nt][0]);
                    mma_bf16(acc[mt][nt], af[mt][0], bf[nt][1]);
                    mma_bf16(acc[mt][nt], af[mt][1], bf[nt][0]);
                }
        }
    }

#pragma unroll
    for (int mt = 0; mt < 2; mt++)
#pragma unroll
        for (int nt = 0; nt < 4; nt++) {
            int row  = n0 + wm * 32 + mt * 16 + (lane >> 2);
            int colb = wn * 32 + nt * 8 + (lane & 3) * 2;
            float bias0 = bias[row], bias1 = bias[row + 8];
            float2 o0 = {acc[mt][nt][0] + bias0, acc[mt][nt][1] + bias0};
            float2 o1 = {acc[mt][nt][2] + bias1, acc[mt][nt][3] + bias1};
            *reinterpret_cast<float2*>(C + ((size_t)s * G3 + row) * BB + colb) = o0;
            *reinterpret_cast<float2*>(C + ((size_t)s * G3 + row + 8) * BB + colb) = o1;
        }
}

// ---------------------------------------------------------------------------
// Persistent scan. 128 CTAs = 32 cg x 4 bg; CTA: 16c x 16b. Fragment-packed
// gmem exchange (R13). NEW: per-warp wait on its OWN 4 producers (private
// flag line per warp), no block barrier before loads, no redundant
// threadfence (release is cumulative over the preceding __syncthreads),
// MUFU-approx gates.
// ---------------------------------------------------------------------------
#define LDW 520
#define OFF_WLO (48 * LDW * 2)
#define OFF_RED (2 * 48 * LDW * 2)
#define SCAN_SMEM (OFF_RED + 8 * 768 * 4)

__global__ __launch_bounds__(256, 1) void scan_layer(
    const float* __restrict__ xlT,    // [S, 3H, B]
    const float* __restrict__ whh_l,  // [3H, H]
    const float* __restrict__ bhh_l,  // [3H]
    const float* __restrict__ h0,     // [B, H]
    float* __restrict__ ysT,          // [S, H, B]
    float* __restrict__ hfin)         // [B, H]
{
    extern __shared__ char sm[];
    __nv_bfloat16* sWhi = reinterpret_cast<__nv_bfloat16*>(sm);
    __nv_bfloat16* sWlo = reinterpret_cast<__nv_bfloat16*>(sm + OFF_WLO);
    float*         red  = reinterpret_cast<float*>(sm + OFF_RED);

    int tid  = threadIdx.x;
    int lane = tid & 31;
    int w    = tid >> 5;
    int cg   = blockIdx.x >> 2;
    int bg   = blockIdx.x & 3;
    int q    = lane >> 3, lr = lane & 7;

    // ---- weight slice -> bf16 hi/lo smem (once) ----
    for (int i = tid; i < 48 * 512; i += 256) {
        int m = i >> 9, k = i & 511;
        int g = m >> 4, c = m & 15;
        float v = whh_l[((size_t)(g * 512 + cg * 16 + c)) * 512 + k];
        __nv_bfloat16 hi = __float2bfloat16(v);
        sWhi[m * LDW + k] = hi;
        sWlo[m * LDW + k] = __float2bfloat16(v - __bfloat162float(hi));
    }
    __syncthreads();

    // ---- preload A fragments for the whole scan ----
    unsigned afh[3][4][4], afl[3][4][4];
#pragma unroll
    for (int mt = 0; mt < 3; mt++)
#pragma unroll
        for (int kt = 0; kt < 4; kt++) {
            int idx = (mt * 16 + (q & 1) * 8 + lr) * LDW + (w * 4 + kt) * 16 + (q >> 1) * 8;
            ldmx4(afh[mt][kt], sWhi + idx);
            ldmx4(afl[mt][kt], sWlo + idx);
        }

    int c_own  = tid >> 4;
    int bl_own = tid & 15;
    int col    = cg * 16 + c_own;
    int bglob  = bg * 16 + bl_own;
    float hp = h0[(size_t)bglob * 512 + col];
    float bR = bhh_l[col], bZ = bhh_l[512 + col], bN = bhh_l[1024 + col];

    // s==0 fragment addressing helpers
    int kp0 = w * 32 + (lane & 3);
    int bb  = bg * 16 + (lane >> 2);

    unsigned* myflag = g_flag + (bg * 32 + cg) * 8;
    const unsigned* wflags = g_flag + (bg * 32 + 4 * w) * 8;   // this warp's 4 producers

    // producer store offset (fragment-packed layout, R13-proven)
    int cpair = c_own >> 1;
    unsigned prod_off = (unsigned)((bg * 8 + (cg >> 2)) * 1024
                        + ((cg & 3) * 2) * 128
                        + ((bl_own & 7) * 4 + (cpair & 3)) * 4
                        + (cpair >> 2) * 2 + (bl_own >> 3));

    for (int s = 0; s < SS; s++) {
        // gate inputs: issue before wait (overlaps)
        const float* xp = xlT + ((size_t)s * G3 + col) * 64 + bglob;
        float xr = __ldg(xp);
        float xz = __ldg(xp + 512 * 64);
        float xn = __ldg(xp + 1024 * 64);

        unsigned bfh[4][4], bfl[4][4];
        if (s > 0) {
            // ---- per-warp wait on its own 4 producers (private flag line) ----
            unsigned tgt = (unsigned)s;
            bool ok;
            do {
                unsigned v = (lane < 4) ? ld_acq(wflags + lane * 8) : tgt;
                ok = __all_sync(0xffffffffu, v >= tgt);
            } while (!ok);

            // ---- 8 coalesced LDG.128 -> fragments ----
            const uint4* reg4 = reinterpret_cast<const uint4*>(g_hx)
                              + (((size_t)(s - 1) * 4 + bg) * 8 + w) * 256;
            uint4 ldv[8];
#pragma unroll
            for (int r4 = 0; r4 < 8; r4++)
                ldv[r4] = __ldg(reg4 + r4 * 32 + lane);
#pragma unroll
            for (int kt = 0; kt < 4; kt++) {
                bfh[kt][0] = ldv[kt * 2].x;     bfh[kt][2] = ldv[kt * 2].y;
                bfh[kt][1] = ldv[kt * 2].z;     bfh[kt][3] = ldv[kt * 2].w;
                bfl[kt][0] = ldv[kt * 2 + 1].x; bfl[kt][2] = ldv[kt * 2 + 1].y;
                bfl[kt][1] = ldv[kt * 2 + 1].z; bfl[kt][3] = ldv[kt * 2 + 1].w;
            }
        } else {
#pragma unroll
            for (int kt = 0; kt < 4; kt++) {
                int kA = kp0 + kt * 8, kB = kA + 4;
                float2 v;
                v = *reinterpret_cast<const float2*>(h0 + (size_t)bb * 512 + 2 * kA);
                f2_hilo(v, bfh[kt][0], bfl[kt][0]);
                v = *reinterpret_cast<const float2*>(h0 + (size_t)bb * 512 + 2 * kB);
                f2_hilo(v, bfh[kt][1], bfl[kt][1]);
                v = *reinterpret_cast<const float2*>(h0 + (size_t)(bb + 8) * 512 + 2 * kA);
                f2_hilo(v, bfh[kt][2], bfl[kt][2]);
                v = *reinterpret_cast<const float2*>(h0 + (size_t)(bb + 8) * 512 + 2 * kB);
                f2_hilo(v, bfh[kt][3], bfl[kt][3]);
            }
        }

        // ---- mma over own K-slice ----
        float acc[3][2][4];
#pragma unroll
        for (int i = 0; i < 3; i++)
#pragma unroll
            for (int j = 0; j < 2; j++)
#pragma unroll
                for (int k = 0; k < 4; k++) acc[i][j][k] = 0.f;

#pragma unroll
        for (int kt = 0; kt < 4; kt++)
#pragma unroll
            for (int mt = 0; mt < 3; mt++) {
                mma_bf16(acc[mt][0], afh[mt][kt], &bfh[kt][0]);
                mma_bf16(acc[mt][0], afh[mt][kt], &bfl[kt][0]);
                mma_bf16(acc[mt][0], afl[mt][kt], &bfh[kt][0]);
                mma_bf16(acc[mt][1], afh[mt][kt], &bfh[kt][2]);
                mma_bf16(acc[mt][1], afh[mt][kt], &bfl[kt][2]);
                mma_bf16(acc[mt][1], afl[mt][kt], &bfh[kt][2]);
            }

        // ---- stash partials ----
#pragma unroll
        for (int mt = 0; mt < 3; mt++)
#pragma unroll
            for (int nt = 0; nt < 2; nt++) {
                int m = mt * 16 + (lane >> 2);
                int n = nt * 8 + (lane & 3) * 2;
                *reinterpret_cast<float2*>(&red[w * 768 + m * 16 + n]) =
                    make_float2(acc[mt][nt][0], acc[mt][nt][1]);
                *reinterpret_cast<float2*>(&red[w * 768 + (m + 8) * 16 + n]) =
                    make_float2(acc[mt][nt][2], acc[mt][nt][3]);
            }
        __syncthreads();   // bar1: partials visible

        // ---- reduce + gates (1 output per thread) ----
        float v0 = 0.f, v1 = 0.f, v2 = 0.f;
#pragma unroll
        for (int ww = 0; ww < 8; ww++) {
            v0 += red[ww * 768 + tid];
            v1 += red[ww * 768 + 256 + tid];
            v2 += red[ww * 768 + 512 + tid];
        }

        float r  = fsig(xr + v0 + bR);
        float z  = fsig(xz + v1 + bZ);
        float nn = ftanh_(xn + r * (v2 + bN));
        float hn = fmaf(z, hp - nn, nn);
        hp = hn;

        // ---- pair-pack + fragment-layout h store (write-once) ----
        float res   = hn - __bfloat162float(__float2bfloat16(hn));
        float hn_p  = __shfl_xor_sync(0xffffffffu, hn, 16);
        float res_p = __shfl_xor_sync(0xffffffffu, res, 16);
        if ((c_own & 1) == 0) {
            unsigned hiu, lou;
            asm("cvt.rn.bf16x2.f32 %0, %1, %2;" : "=r"(hiu) : "f"(hn_p), "f"(hn));
            asm("cvt.rn.bf16x2.f32 %0, %1, %2;" : "=r"(lou) : "f"(res_p), "f"(res));
            unsigned* dst = g_hx + (size_t)s * 32768 + prod_off;
            dst[0]   = hiu;
            dst[128] = lou;
        }

        __syncthreads();   // bar2: all h stores done (+ red reuse safe)
        if (tid == 0 && s < SS - 1)
            st_rel(myflag, (unsigned)(s + 1));   // release is cumulative: no fence needed

        // outputs off the critical path (after the flag release)
        ysT[((size_t)s * 512 + col) * 64 + bglob] = hn;
        if (s == SS - 1) hfin[(size_t)bglob * 512 + col] = hn;
    }
}

// ---------------------------------------------------------------------------
// [S,H,B] -> [S,B,H]
// ---------------------------------------------------------------------------
__global__ __launch_bounds__(256) void transpose_out(
    const float* __restrict__ in, float* __restrict__ out)
{
    __shared__ float t[32][33];
    int s  = blockIdx.z;
    int h0 = blockIdx.x * 32;
    int b0 = blockIdx.y * 32;
    int tx = threadIdx.x, ty = threadIdx.y;

#pragma unroll
    for (int r = 0; r < 4; r++)
        t[ty + r * 8][tx] = in[((size_t)s * HH + h0 + ty + r * 8) * BB + b0 + tx];
    __syncthreads();
#pragma unroll
    for (int r = 0; r < 4; r++)
        out[((size_t)s * BB + b0 + ty + r * 8) * HH + h0 + tx] = t[tx][ty + r * 8];
}

// ---------------------------------------------------------------------------
extern "C" void kernel_launch(void* const* d_in, const int* in_sizes, int n_in,
                              void* d_out, int out_size)
{
    const float* x   = (const float*)d_in[0];
    const float* hx  = (const float*)d_in[1];
    const float* wih = (const float*)d_in[2];
    const float* whh = (const float*)d_in[3];
    const float* bih = (const float*)d_in[4];
    const float* bhh = (const float*)d_in[5];

    float* out    = (float*)d_out;
    float* hidden = out + (size_t)SS * BB * HH;

    float *p_xlin, *p_T1;
    __nv_bfloat16 *p_bhi, *p_blo, *p_whi, *p_wlo;
    cudaGetSymbolAddress((void**)&p_xlin, g_xlin);
    cudaGetSymbolAddress((void**)&p_T1,   g_T1);
    cudaGetSymbolAddress((void**)&p_bhi,  g_bhi);
    cudaGetSymbolAddress((void**)&p_blo,  g_blo);
    cudaGetSymbolAddress((void**)&p_whi,  g_whi);
    cudaGetSymbolAddress((void**)&p_wlo,  g_wlo);

    static int attr_done = 0;
    if (!attr_done) {
        cudaFuncSetAttribute(scan_layer,
                             cudaFuncAttributeMaxDynamicSharedMemorySize, SCAN_SMEM);
        attr_done = 1;
    }

    const unsigned NWB = (G3 * II) / 256;                       // 3072
    const unsigned NXB = (unsigned)((size_t)SS * BB * II / 256); // 262144
    dim3 ggrid(SS, G3 / BMN);
    dim3 tgrid(HH / 32, BB / 32, SS);
    dim3 tblk(32, 8);

    for (int l = 0; l < LL; l++) {
        const float* Xsrc = (l == 0) ? x : p_T1;

        // launch #0/#3: split W + split X + reset flags
        prep_layer<<<NWB + 1 + NXB, 256>>>(Xsrc, wih + (size_t)l * G3 * II,
                                           p_bhi, p_blo, p_whi, p_wlo);

        // launch #1/#4: input-projection GEMM (native transposed output)
        if (l == 0)
            gemm_xlinT<0><<<ggrid, 256>>>(p_whi, p_wlo, p_bhi, p_blo,
                                          bih + (size_t)l * G3, p_xlin);
        else
            gemm_xlinT<1><<<ggrid, 256>>>(p_whi, p_wlo, p_bhi, p_blo,
                                          bih + (size_t)l * G3, p_xlin);

        // launch #2/#5 (ncu -s 5 captures the layer-2 scan)
        scan_layer<<<128, 256, SCAN_SMEM>>>(
            p_xlin,
            whh + (size_t)l * G3 * HH,
            bhh + (size_t)l * G3,
            hx  + (size_t)l * BB * HH,
            p_T1,
            hidden + (size_t)l * BB * HH);
    }

    transpose_out<<<tgrid, tblk>>>(p_T1, out);
}

// round 15
// speedup vs baseline: 1.4332x; 1.4332x over previous
#include <cuda_runtime.h>
#include <cuda_bf16.h>
#include <math.h>

typedef unsigned long long ull;

#define SS 2048
#define BB 64
#define II 512
#define HH 512
#define G3 1536   // 3*H
#define LL 2

// ---- Scratch (allocation-free rule: __device__ globals) --------------------
__device__ float g_xlin[(size_t)SS * G3 * BB];   // [S,3H,B]
__device__ float g_T1  [(size_t)SS * HH * BB];   // [S,H,B] ys (both layers)
__device__ __nv_bfloat16 g_bhi[(size_t)SS * BB * II];  // X split hi
__device__ __nv_bfloat16 g_blo[(size_t)SS * BB * II];  // X split lo
__device__ __nv_bfloat16 g_whi[(size_t)G3 * II];
__device__ __nv_bfloat16 g_wlo[(size_t)G3 * II];
// h exchange, consumer-fragment-packed: [s][bg 4][w 8][1024 u32]
__device__ unsigned g_hx[(size_t)SS * 4 * 8 * 1024];
// per-CTA step flags: [bg 4][cg 32] -> one 128B line per batch group (R13 layout)
__device__ unsigned g_flag[128];

// ---------------------------------------------------------------------------
// prep: split W (bf16 hi/lo), split X, reset flags — one kernel
// ---------------------------------------------------------------------------
__global__ __launch_bounds__(256) void prep_layer(
    const float* __restrict__ X, const float* __restrict__ W,
    __nv_bfloat16* __restrict__ xh, __nv_bfloat16* __restrict__ xl,
    __nv_bfloat16* __restrict__ wh, __nv_bfloat16* __restrict__ wl)
{
    const unsigned NWB = (G3 * II) / 256;      // 3072
    unsigned bid = blockIdx.x;
    int tid = threadIdx.x;
    if (bid < NWB) {
        size_t i = (size_t)bid * 256 + tid;
        float v = W[i];
        __nv_bfloat16 h = __float2bfloat16(v);
        wh[i] = h; wl[i] = __float2bfloat16(v - __bfloat162float(h));
    } else if (bid == NWB) {
        if (tid < 128) g_flag[tid] = 0;
    } else {
        size_t i = (size_t)(bid - NWB - 1) * 256 + tid;
        float v = X[i];
        __nv_bfloat16 h = __float2bfloat16(v);
        xh[i] = h; xl[i] = __float2bfloat16(v - __bfloat162float(h));
    }
}

// ---------------------------------------------------------------------------
__device__ __forceinline__ void mma_bf16(float* d, const unsigned* a, const unsigned* b)
{
    asm volatile(
        "mma.sync.aligned.m16n8k16.row.col.f32.bf16.bf16.f32 "
        "{%0,%1,%2,%3},{%4,%5,%6,%7},{%8,%9},{%0,%1,%2,%3};"
        : "+f"(d[0]), "+f"(d[1]), "+f"(d[2]), "+f"(d[3])
        : "r"(a[0]), "r"(a[1]), "r"(a[2]), "r"(a[3]), "r"(b[0]), "r"(b[1]));
}

__device__ __forceinline__ void ldmx4(unsigned* r, const __nv_bfloat16* p)
{
    unsigned addr = (unsigned)__cvta_generic_to_shared(p);
    asm volatile("ldmatrix.sync.aligned.m8n8.x4.shared.b16 {%0,%1,%2,%3}, [%4];"
                 : "=r"(r[0]), "=r"(r[1]), "=r"(r[2]), "=r"(r[3]) : "r"(addr));
}

__device__ __forceinline__ unsigned ld_acq(const unsigned* p)
{
    unsigned v;
    asm volatile("ld.acquire.gpu.global.u32 %0, [%1];" : "=r"(v) : "l"(p));
    return v;
}

__device__ __forceinline__ void st_rel(unsigned* p, unsigned v)
{
    asm volatile("st.release.gpu.global.u32 [%0], %1;" :: "l"(p), "r"(v) : "memory");
}

__device__ __forceinline__ float fast_ex2(float x)
{ float y; asm("ex2.approx.f32 %0, %1;" : "=f"(y) : "f"(x)); return y; }
__device__ __forceinline__ float fast_rcp(float x)
{ float y; asm("rcp.approx.f32 %0, %1;" : "=f"(y) : "f"(x)); return y; }
__device__ __forceinline__ float fsig(float x)
{ return fast_rcp(1.f + fast_ex2(-1.44269504f * x)); }
__device__ __forceinline__ float ftanh_(float x)
{ return fmaf(2.f, fast_rcp(1.f + fast_ex2(-2.88539008f * x)), -1.f); }

// pack float2 -> bf16x2 + residual pair
__device__ __forceinline__ void f2_hilo(float2 v, unsigned& hi, unsigned& lo)
{
    asm("cvt.rn.bf16x2.f32 %0, %1, %2;" : "=r"(hi) : "f"(v.y), "f"(v.x));
    __nv_bfloat162 hb = *reinterpret_cast<__nv_bfloat162*>(&hi);
    float rx = v.x - __bfloat162float(hb.x);
    float ry = v.y - __bfloat162float(hb.y);
    asm("cvt.rn.bf16x2.f32 %0, %1, %2;" : "=r"(lo) : "f"(ry), "f"(rx));
}

// ---------------------------------------------------------------------------
// xlinT[s, n, b] = sum_k W[n,k] * X[s,b,k] + bias[n]  (bf16x3 mma)
// BT=0: X rows [b][k].  BT=1: X stored [s][k][b].
// ---------------------------------------------------------------------------
#define BMN 128
#define BNB 64
#define BK  32
#define LDT 40

template <int BT>
__global__ __launch_bounds__(256, 2) void gemm_xlinT(
    const __nv_bfloat16* __restrict__ Whi, const __nv_bfloat16* __restrict__ Wlo,
    const __nv_bfloat16* __restrict__ Xhi, const __nv_bfloat16* __restrict__ Xlo,
    const float* __restrict__ bias, float* __restrict__ C)
{
    __shared__ __align__(16) __nv_bfloat16 sA[2][BMN * LDT];
    __shared__ __align__(16) __nv_bfloat16 sB[2][BNB * LDT];

    int tid  = threadIdx.x;
    int s    = blockIdx.x;
    int n0   = blockIdx.y * BMN;
    int w    = tid >> 5, lane = tid & 31;
    int wm   = w >> 1,   wn   = w & 1;

    const __nv_bfloat16* Xh = Xhi + (size_t)s * BB * II;
    const __nv_bfloat16* Xl = Xlo + (size_t)s * BB * II;

    float acc[2][4][4];
#pragma unroll
    for (int i = 0; i < 2; i++)
#pragma unroll
        for (int j = 0; j < 4; j++)
#pragma unroll
            for (int k = 0; k < 4; k++) acc[i][j][k] = 0.f;

    for (int k0 = 0; k0 < II; k0 += BK) {
        __syncthreads();
#pragma unroll
        for (int v = 0; v < 2; v++) {
            int fi = tid + v * 256;
            int r  = fi >> 2, kq = fi & 3;
            const uint4* gh = reinterpret_cast<const uint4*>(Whi + (size_t)(n0 + r) * II + k0);
            const uint4* gl = reinterpret_cast<const uint4*>(Wlo + (size_t)(n0 + r) * II + k0);
            reinterpret_cast<uint4*>(&sA[0][(size_t)r * LDT])[kq] = gh[kq];
            reinterpret_cast<uint4*>(&sA[1][(size_t)r * LDT])[kq] = gl[kq];
        }
        if (BT == 0) {
            int r = tid >> 2, kq = tid & 3;
            const uint4* gh = reinterpret_cast<const uint4*>(Xh + (size_t)r * II + k0);
            const uint4* gl = reinterpret_cast<const uint4*>(Xl + (size_t)r * II + k0);
            reinterpret_cast<uint4*>(&sB[0][(size_t)r * LDT])[kq] = gh[kq];
            reinterpret_cast<uint4*>(&sB[1][(size_t)r * LDT])[kq] = gl[kq];
        } else {
            int kk = tid >> 3;
            int bo = (tid & 7) * 8;
            uint4 vh = *reinterpret_cast<const uint4*>(Xh + (size_t)(k0 + kk) * BB + bo);
            uint4 vl = *reinterpret_cast<const uint4*>(Xl + (size_t)(k0 + kk) * BB + bo);
            const unsigned short* ph = reinterpret_cast<const unsigned short*>(&vh);
            const unsigned short* pl = reinterpret_cast<const unsigned short*>(&vl);
            unsigned short* s0 = reinterpret_cast<unsigned short*>(sB[0]);
            unsigned short* s1 = reinterpret_cast<unsigned short*>(sB[1]);
#pragma unroll
            for (int e = 0; e < 8; e++) {
                s0[(size_t)(bo + e) * LDT + kk] = ph[e];
                s1[(size_t)(bo + e) * LDT + kk] = pl[e];
            }
        }
        __syncthreads();

#pragma unroll
        for (int kh = 0; kh < 2; kh++) {
            int koff = kh * 16;
            unsigned af[2][2][4];
            unsigned bf[4][2][2];
            int q = lane >> 3, lr = lane & 7;
#pragma unroll
            for (int mt = 0; mt < 2; mt++) {
                const __nv_bfloat16* pa =
                    &sA[0][(size_t)(wm * 32 + mt * 16 + (q & 1) * 8 + lr) * LDT + koff + (q >> 1) * 8];
                ldmx4(af[mt][0], pa);
                ldmx4(af[mt][1], pa + BMN * LDT);
            }
#pragma unroll
            for (int j = 0; j < 2; j++) {
                int ntile = 2 * j + (q >> 1);
                const __nv_bfloat16* pb =
                    &sB[0][(size_t)(wn * 32 + ntile * 8 + lr) * LDT + koff + (q & 1) * 8];
                unsigned t[4];
                ldmx4(t, pb);
                bf[2 * j][0][0] = t[0]; bf[2 * j][0][1] = t[1];
                bf[2 * j + 1][0][0] = t[2]; bf[2 * j + 1][0][1] = t[3];
                ldmx4(t, pb + BNB * LDT);
                bf[2 * j][1][0] = t[0]; bf[2 * j][1][1] = t[1];
                bf[2 * j + 1][1][0] = t[2]; bf[2 * j + 1][1][1] = t[3];
            }
#pragma unroll
            for (int mt = 0; mt < 2; mt++)
#pragma unroll
                for (int nt = 0; nt < 4; nt++) {
                    mma_bf16(acc[mt][nt], af[mt][0], bf[nt][0]);
                    mma_bf16(acc[mt][nt], af[mt][0], bf[nt][1]);
                    mma_bf16(acc[mt][nt], af[mt][1], bf[nt][0]);
                }
        }
    }

#pragma unroll
    for (int mt = 0; mt < 2; mt++)
#pragma unroll
        for (int nt = 0; nt < 4; nt++) {
            int row  = n0 + wm * 32 + mt * 16 + (lane >> 2);
            int colb = wn * 32 + nt * 8 + (lane & 3) * 2;
            float bias0 = bias[row], bias1 = bias[row + 8];
            float2 o0 = {acc[mt][nt][0] + bias0, acc[mt][nt][1] + bias0};
            float2 o1 = {acc[mt][nt][2] + bias1, acc[mt][nt][3] + bias1};
            *reinterpret_cast<float2*>(C + ((size_t)s * G3 + row) * BB + colb) = o0;
            *reinterpret_cast<float2*>(C + ((size_t)s * G3 + row + 8) * BB + colb) = o1;
        }
}

// ---------------------------------------------------------------------------
// Persistent scan (R13 sync skeleton: warp-0 polls all 32 flags in one line,
// __syncthreads broadcast). Fragment-packed gmem exchange. MUFU gates,
// fence-free release, outputs after the release.
// ---------------------------------------------------------------------------
#define LDW 520
#define OFF_WLO (48 * LDW * 2)
#define OFF_RED (2 * 48 * LDW * 2)
#define SCAN_SMEM (OFF_RED + 8 * 768 * 4)

__global__ __launch_bounds__(256, 1) void scan_layer(
    const float* __restrict__ xlT,    // [S, 3H, B]
    const float* __restrict__ whh_l,  // [3H, H]
    const float* __restrict__ bhh_l,  // [3H]
    const float* __restrict__ h0,     // [B, H]
    float* __restrict__ ysT,          // [S, H, B]
    float* __restrict__ hfin)         // [B, H]
{
    extern __shared__ char sm[];
    __nv_bfloat16* sWhi = reinterpret_cast<__nv_bfloat16*>(sm);
    __nv_bfloat16* sWlo = reinterpret_cast<__nv_bfloat16*>(sm + OFF_WLO);
    float*         red  = reinterpret_cast<float*>(sm + OFF_RED);

    int tid  = threadIdx.x;
    int lane = tid & 31;
    int w    = tid >> 5;
    int cg   = blockIdx.x >> 2;
    int bg   = blockIdx.x & 3;
    int q    = lane >> 3, lr = lane & 7;

    // ---- weight slice -> bf16 hi/lo smem (once) ----
    for (int i = tid; i < 48 * 512; i += 256) {
        int m = i >> 9, k = i & 511;
        int g = m >> 4, c = m & 15;
        float v = whh_l[((size_t)(g * 512 + cg * 16 + c)) * 512 + k];
        __nv_bfloat16 hi = __float2bfloat16(v);
        sWhi[m * LDW + k] = hi;
        sWlo[m * LDW + k] = __float2bfloat16(v - __bfloat162float(hi));
    }
    __syncthreads();

    // ---- preload A fragments for the whole scan ----
    unsigned afh[3][4][4], afl[3][4][4];
#pragma unroll
    for (int mt = 0; mt < 3; mt++)
#pragma unroll
        for (int kt = 0; kt < 4; kt++) {
            int idx = (mt * 16 + (q & 1) * 8 + lr) * LDW + (w * 4 + kt) * 16 + (q >> 1) * 8;
            ldmx4(afh[mt][kt], sWhi + idx);
            ldmx4(afl[mt][kt], sWlo + idx);
        }

    int c_own  = tid >> 4;
    int bl_own = tid & 15;
    int col    = cg * 16 + c_own;
    int bglob  = bg * 16 + bl_own;
    float hp = h0[(size_t)bglob * 512 + col];
    float bR = bhh_l[col], bZ = bhh_l[512 + col], bN = bhh_l[1024 + col];

    // s==0 fragment addressing helpers
    int kp0 = w * 32 + (lane & 3);
    int bb  = bg * 16 + (lane >> 2);

    unsigned* myflag = g_flag + bg * 32 + cg;
    const unsigned* bgflags = g_flag + bg * 32;

    // producer store offset (fragment-packed layout, R13-proven)
    int cpair = c_own >> 1;
    unsigned prod_off = (unsigned)((bg * 8 + (cg >> 2)) * 1024
                        + ((cg & 3) * 2) * 128
                        + ((bl_own & 7) * 4 + (cpair & 3)) * 4
                        + (cpair >> 2) * 2 + (bl_own >> 3));

    for (int s = 0; s < SS; s++) {
        // gate inputs: issue before wait (overlaps)
        const float* xp = xlT + ((size_t)s * G3 + col) * 64 + bglob;
        float xr = __ldg(xp);
        float xz = __ldg(xp + 512 * 64);
        float xn = __ldg(xp + 1024 * 64);

        unsigned bfh[4][4], bfl[4][4];
        if (s > 0) {
            // ---- warp-0 poll of all 32 producer flags (one 128B line) ----
            if (w == 0) {
                unsigned tgt = (unsigned)s;
                bool ok;
                do {
                    unsigned v = ld_acq(bgflags + lane);
                    ok = __all_sync(0xffffffffu, v >= tgt);
                } while (!ok);
            }
            __syncthreads();

            // ---- 8 coalesced LDG.128 -> fragments ----
            const uint4* reg4 = reinterpret_cast<const uint4*>(g_hx)
                              + (((size_t)(s - 1) * 4 + bg) * 8 + w) * 256;
            uint4 ldv[8];
#pragma unroll
            for (int r4 = 0; r4 < 8; r4++)
                ldv[r4] = __ldg(reg4 + r4 * 32 + lane);
#pragma unroll
            for (int kt = 0; kt < 4; kt++) {
                bfh[kt][0] = ldv[kt * 2].x;     bfh[kt][2] = ldv[kt * 2].y;
                bfh[kt][1] = ldv[kt * 2].z;     bfh[kt][3] = ldv[kt * 2].w;
                bfl[kt][0] = ldv[kt * 2 + 1].x; bfl[kt][2] = ldv[kt * 2 + 1].y;
                bfl[kt][1] = ldv[kt * 2 + 1].z; bfl[kt][3] = ldv[kt * 2 + 1].w;
            }
        } else {
#pragma unroll
            for (int kt = 0; kt < 4; kt++) {
                int kA = kp0 + kt * 8, kB = kA + 4;
                float2 v;
                v = *reinterpret_cast<const float2*>(h0 + (size_t)bb * 512 + 2 * kA);
                f2_hilo(v, bfh[kt][0], bfl[kt][0]);
                v = *reinterpret_cast<const float2*>(h0 + (size_t)bb * 512 + 2 * kB);
                f2_hilo(v, bfh[kt][1], bfl[kt][1]);
                v = *reinterpret_cast<const float2*>(h0 + (size_t)(bb + 8) * 512 + 2 * kA);
                f2_hilo(v, bfh[kt][2], bfl[kt][2]);
                v = *reinterpret_cast<const float2*>(h0 + (size_t)(bb + 8) * 512 + 2 * kB);
                f2_hilo(v, bfh[kt][3], bfl[kt][3]);
            }
        }

        // ---- mma over own K-slice ----
        float acc[3][2][4];
#pragma unroll
        for (int i = 0; i < 3; i++)
#pragma unroll
            for (int j = 0; j < 2; j++)
#pragma unroll
                for (int k = 0; k < 4; k++) acc[i][j][k] = 0.f;

#pragma unroll
        for (int kt = 0; kt < 4; kt++)
#pragma unroll
            for (int mt = 0; mt < 3; mt++) {
                mma_bf16(acc[mt][0], afh[mt][kt], &bfh[kt][0]);
                mma_bf16(acc[mt][0], afh[mt][kt], &bfl[kt][0]);
                mma_bf16(acc[mt][0], afl[mt][kt], &bfh[kt][0]);
                mma_bf16(acc[mt][1], afh[mt][kt], &bfh[kt][2]);
                mma_bf16(acc[mt][1], afh[mt][kt], &bfl[kt][2]);
                mma_bf16(acc[mt][1], afl[mt][kt], &bfh[kt][2]);
            }

        // ---- stash partials ----
#pragma unroll
        for (int mt = 0; mt < 3; mt++)
#pragma unroll
            for (int nt = 0; nt < 2; nt++) {
                int m = mt * 16 + (lane >> 2);
                int n = nt * 8 + (lane & 3) * 2;
                *reinterpret_cast<float2*>(&red[w * 768 + m * 16 + n]) =
                    make_float2(acc[mt][nt][0], acc[mt][nt][1]);
                *reinterpret_cast<float2*>(&red[w * 768 + (m + 8) * 16 + n]) =
                    make_float2(acc[mt][nt][2], acc[mt][nt][3]);
            }
        __syncthreads();   // bar1: partials visible

        // ---- reduce + gates (1 output per thread) ----
        float v0 = 0.f, v1 = 0.f, v2 = 0.f;
#pragma unroll
        for (int ww = 0; ww < 8; ww++) {
            v0 += red[ww * 768 + tid];
            v1 += red[ww * 768 + 256 + tid];
            v2 += red[ww * 768 + 512 + tid];
        }

        float r  = fsig(xr + v0 + bR);
        float z  = fsig(xz + v1 + bZ);
        float nn = ftanh_(xn + r * (v2 + bN));
        float hn = fmaf(z, hp - nn, nn);
        hp = hn;

        // ---- pair-pack + fragment-layout h store (write-once) ----
        float res   = hn - __bfloat162float(__float2bfloat16(hn));
        float hn_p  = __shfl_xor_sync(0xffffffffu, hn, 16);
        float res_p = __shfl_xor_sync(0xffffffffu, res, 16);
        if ((c_own & 1) == 0) {
            unsigned hiu, lou;
            asm("cvt.rn.bf16x2.f32 %0, %1, %2;" : "=r"(hiu) : "f"(hn_p), "f"(hn));
            asm("cvt.rn.bf16x2.f32 %0, %1, %2;" : "=r"(lou) : "f"(res_p), "f"(res));
            unsigned* dst = g_hx + (size_t)s * 32768 + prod_off;
            dst[0]   = hiu;
            dst[128] = lou;
        }

        __syncthreads();   // bar2: all h stores done (+ red reuse safe)
        if (tid == 0 && s < SS - 1)
            st_rel(myflag, (unsigned)(s + 1));   // release cumulative over bar2: no fence

        // outputs off the inter-CTA critical path
        ysT[((size_t)s * 512 + col) * 64 + bglob] = hn;
        if (s == SS - 1) hfin[(size_t)bglob * 512 + col] = hn;
    }
}

// ---------------------------------------------------------------------------
// [S,H,B] -> [S,B,H]
// ---------------------------------------------------------------------------
__global__ __launch_bounds__(256) void transpose_out(
    const float* __restrict__ in, float* __restrict__ out)
{
    __shared__ float t[32][33];
    int s  = blockIdx.z;
    int h0 = blockIdx.x * 32;
    int b0 = blockIdx.y * 32;
    int tx = threadIdx.x, ty = threadIdx.y;

#pragma unroll
    for (int r = 0; r < 4; r++)
        t[ty + r * 8][tx] = in[((size_t)s * HH + h0 + ty + r * 8) * BB + b0 + tx];
    __syncthreads();
#pragma unroll
    for (int r = 0; r < 4; r++)
        out[((size_t)s * BB + b0 + ty + r * 8) * HH + h0 + tx] = t[tx][ty + r * 8];
}

// ---------------------------------------------------------------------------
extern "C" void kernel_launch(void* const* d_in, const int* in_sizes, int n_in,
                              void* d_out, int out_size)
{
    const float* x   = (const float*)d_in[0];
    const float* hx  = (const float*)d_in[1];
    const float* wih = (const float*)d_in[2];
    const float* whh = (const float*)d_in[3];
    const float* bih = (const float*)d_in[4];
    const float* bhh = (const float*)d_in[5];

    float* out    = (float*)d_out;
    float* hidden = out + (size_t)SS * BB * HH;

    float *p_xlin, *p_T1;
    __nv_bfloat16 *p_bhi, *p_blo, *p_whi, *p_wlo;
    cudaGetSymbolAddress((void**)&p_xlin, g_xlin);
    cudaGetSymbolAddress((void**)&p_T1,   g_T1);
    cudaGetSymbolAddress((void**)&p_bhi,  g_bhi);
    cudaGetSymbolAddress((void**)&p_blo,  g_blo);
    cudaGetSymbolAddress((void**)&p_whi,  g_whi);
    cudaGetSymbolAddress((void**)&p_wlo,  g_wlo);

    static int attr_done = 0;
    if (!attr_done) {
        cudaFuncSetAttribute(scan_layer,
                             cudaFuncAttributeMaxDynamicSharedMemorySize, SCAN_SMEM);
        attr_done = 1;
    }

    const unsigned NWB = (G3 * II) / 256;                        // 3072
    const unsigned NXB = (unsigned)((size_t)SS * BB * II / 256); // 262144
    dim3 ggrid(SS, G3 / BMN);
    dim3 tgrid(HH / 32, BB / 32, SS);
    dim3 tblk(32, 8);

    for (int l = 0; l < LL; l++) {
        const float* Xsrc = (l == 0) ? x : p_T1;

        prep_layer<<<NWB + 1 + NXB, 256>>>(Xsrc, wih + (size_t)l * G3 * II,
                                           p_bhi, p_blo, p_whi, p_wlo);

        if (l == 0)
            gemm_xlinT<0><<<ggrid, 256>>>(p_whi, p_wlo, p_bhi, p_blo,
                                          bih + (size_t)l * G3, p_xlin);
        else
            gemm_xlinT<1><<<ggrid, 256>>>(p_whi, p_wlo, p_bhi, p_blo,
                                          bih + (size_t)l * G3, p_xlin);

        scan_layer<<<128, 256, SCAN_SMEM>>>(
            p_xlin,
            whh + (size_t)l * G3 * HH,
            bhh + (size_t)l * G3,
            hx  + (size_t)l * BB * HH,
            p_T1,
            hidden + (size_t)l * BB * HH);
    }

    transpose_out<<<tgrid, tblk>>>(p_T1, out);
}